// round 14
// baseline (speedup 1.0000x reference)
#include <cuda_runtime.h>
#include <cstdint>

#define B_   4
#define T_   2048
#define HIN_ 1024
#define H_   16
#define E_   64
#define HE_  (H_ * E_)   // 1024
#define BT_  (B_ * T_)   // 8192
#define NSPLIT 2
#define TSPLIT (T_ / NSPLIT)   // 1024 keys per split

// Persistent scratch (no allocations allowed in kernel_launch).
__device__ float g_Q[BT_ * HE_];
__device__ float g_K[BT_ * HE_];
__device__ float g_V[BT_ * HE_];
__device__ float g_Op[NSPLIT * BT_ * HE_];   // unnormalized partial O
__device__ float g_m[NSPLIT * BT_ * H_];     // running max per row
__device__ float g_l[NSPLIT * BT_ * H_];     // running sum per row

// ---------------------------------------------------------------------------
// Packed fp32x2 helpers (Blackwell FFMA2 via PTX f32x2)
// ---------------------------------------------------------------------------
typedef unsigned long long u64;

__device__ __forceinline__ u64 pack2(float lo, float hi) {
    u64 r;
    asm("mov.b64 %0, {%1,%2};" : "=l"(r) : "f"(lo), "f"(hi));
    return r;
}
__device__ __forceinline__ float2 unpack2(u64 v) {
    float2 r;
    asm("mov.b64 {%0,%1}, %2;" : "=f"(r.x), "=f"(r.y) : "l"(v));
    return r;
}
__device__ __forceinline__ void fma2(u64& d, u64 a, u64 b) {
    asm("fma.rn.f32x2 %0, %1, %2, %0;" : "+l"(d) : "l"(a), "l"(b));
}
__device__ __forceinline__ u64 mul2(u64 a, u64 b) {
    u64 r;
    asm("mul.rn.f32x2 %0, %1, %2;" : "=l"(r) : "l"(a), "l"(b));
    return r;
}

// ---------------------------------------------------------------------------
// Projection GEMM, KV-fused (z=0: Q; z=1: K+V share the A tile).
// CTA tile 64x64, BK=16, 128 threads, 8x4 micro-tile per output,
// double-buffered smem, one __syncthreads per k-chunk.
// NEW: A stored DUPLICATED in smem as (a,a) u64 — broadcast operand is read
// by LDS.64 directly; the per-kk pack2 MOVs are gone (packed once in loader).
// ---------------------------------------------------------------------------
__global__ __launch_bounds__(128) void proj_gemm(const float* __restrict__ Aq,
                                                 const float* __restrict__ Akv,
                                                 const float* __restrict__ Wq,
                                                 const float* __restrict__ Wk,
                                                 const float* __restrict__ Wv,
                                                 float scale) {
    __shared__ u64 AsT[2][16][64];        // [buf][k][m] duplicated pairs, 16 KB
    __shared__ float Ws[2][2][16][68];    // [buf][mat][k][n], padded rows

    const int fused = blockIdx.z;         // 0: Q, 1: K+V
    const float* __restrict__ A  = fused ? Akv : Aq;
    const float* __restrict__ W0 = fused ? Wk : Wq;
    const float* __restrict__ W1 = Wv;    // used only when fused
    float* __restrict__ C0 = fused ? g_K : g_Q;
    float* __restrict__ C1 = g_V;

    const int tid = threadIdx.x;
    const int ty = tid >> 4;          // 0..7  (8 rows each)
    const int tx = tid & 15;          // 0..15 (4 cols each)
    const int bm = blockIdx.y << 6;
    const int bn = blockIdx.x << 6;

    // A loader: 64 rows x 16 k; thread -> row tid/2, 8 k at (tid&1)*8
    const int ar = tid >> 1;
    const int ac = (tid & 1) << 3;
    // W loader: 16 k-rows x 64 cols; thread -> row tid/8, 8 cols at (tid&7)*8
    const int wr = tid >> 3;
    const int wc = (tid & 7) << 3;

    const float* Ap  = A + (size_t)(bm + ar) * HIN_ + ac;
    const float* W0p = W0 + (size_t)wr * HE_ + bn + wc;
    const float* W1p = W1 + (size_t)wr * HE_ + bn + wc;

    u64 acc0[8][2], acc1[8][2];
#pragma unroll
    for (int i = 0; i < 8; i++) {
        acc0[i][0] = 0ull; acc0[i][1] = 0ull;
        acc1[i][0] = 0ull; acc1[i][1] = 0ull;
    }

    // swizzle: storage (u64) col of (k, m) = m ^ (((k>>2)&3)<<2)
    {   // prologue: chunk 0
        float4 a0 = *(const float4*)(Ap);
        float4 a1 = *(const float4*)(Ap + 4);
        float av[8] = {a0.x, a0.y, a0.z, a0.w, a1.x, a1.y, a1.z, a1.w};
#pragma unroll
        for (int j = 0; j < 8; j++) {
            int k = ac + j;
            AsT[0][k][ar ^ (((k >> 2) & 3) << 2)] = pack2(av[j], av[j]);
        }
        *(float4*)&Ws[0][0][wr][wc]     = *(const float4*)(W0p);
        *(float4*)&Ws[0][0][wr][wc + 4] = *(const float4*)(W0p + 4);
        if (fused) {
            *(float4*)&Ws[0][1][wr][wc]     = *(const float4*)(W1p);
            *(float4*)&Ws[0][1][wr][wc + 4] = *(const float4*)(W1p + 4);
        }
    }
    __syncthreads();

    int buf = 0;
    for (int it = 1; it <= 64; it++) {
        float4 a0, a1, wa0, wa1, wb0, wb1;
        if (it < 64) {   // prefetch chunk it
            a0 = *(const float4*)(Ap + it * 16);
            a1 = *(const float4*)(Ap + it * 16 + 4);
            wa0 = *(const float4*)(W0p + (size_t)it * 16 * HE_);
            wa1 = *(const float4*)(W0p + (size_t)it * 16 * HE_ + 4);
            if (fused) {
                wb0 = *(const float4*)(W1p + (size_t)it * 16 * HE_);
                wb1 = *(const float4*)(W1p + (size_t)it * 16 * HE_ + 4);
            }
        }

        // compute chunk it-1 from buf
#pragma unroll
        for (int kk = 0; kk < 16; kk++) {
            int cx = ((kk >> 2) & 3) << 2;
            const u64* arow = AsT[buf][kk];
            u64 ad[8];
#pragma unroll
            for (int i = 0; i < 8; i++)
                ad[i] = arow[((ty << 3) | i) ^ cx];   // LDS.64 broadcast
            float4 w4 = *(const float4*)&Ws[buf][0][kk][tx << 2];
            u64 wp0 = pack2(w4.x, w4.y);
            u64 wp1 = pack2(w4.z, w4.w);
#pragma unroll
            for (int i = 0; i < 8; i++) {
                fma2(acc0[i][0], ad[i], wp0);
                fma2(acc0[i][1], ad[i], wp1);
            }
            if (fused) {
                float4 v4 = *(const float4*)&Ws[buf][1][kk][tx << 2];
                u64 vp0 = pack2(v4.x, v4.y);
                u64 vp1 = pack2(v4.z, v4.w);
#pragma unroll
                for (int i = 0; i < 8; i++) {
                    fma2(acc1[i][0], ad[i], vp0);
                    fma2(acc1[i][1], ad[i], vp1);
                }
            }
        }

        if (it < 64) {
            int nb = buf ^ 1;
            float av[8] = {a0.x, a0.y, a0.z, a0.w, a1.x, a1.y, a1.z, a1.w};
#pragma unroll
            for (int j = 0; j < 8; j++) {
                int k = ac + j;
                AsT[nb][k][ar ^ (((k >> 2) & 3) << 2)] = pack2(av[j], av[j]);
            }
            *(float4*)&Ws[nb][0][wr][wc]     = wa0;
            *(float4*)&Ws[nb][0][wr][wc + 4] = wa1;
            if (fused) {
                *(float4*)&Ws[nb][1][wr][wc]     = wb0;
                *(float4*)&Ws[nb][1][wr][wc + 4] = wb1;
            }
            __syncthreads();
            buf = nb;
        }
    }

    // Epilogue: Q and K carry the softmax scale; V is unscaled.
#pragma unroll
    for (int i = 0; i < 8; i++) {
        float2 p0 = unpack2(acc0[i][0]);
        float2 p1 = unpack2(acc0[i][1]);
        float4 r = make_float4(p0.x * scale, p0.y * scale,
                               p1.x * scale, p1.y * scale);
        *(float4*)&C0[(size_t)(bm + (ty << 3) + i) * HE_ + bn + (tx << 2)] = r;
    }
    if (fused) {
#pragma unroll
        for (int i = 0; i < 8; i++) {
            float2 p0 = unpack2(acc1[i][0]);
            float2 p1 = unpack2(acc1[i][1]);
            float4 r = make_float4(p0.x, p0.y, p1.x, p1.y);
            *(float4*)&C1[(size_t)(bm + (ty << 3) + i) * HE_ + bn + (tx << 2)] = r;
        }
    }
}

// ---------------------------------------------------------------------------
// Flash attention, split-K. P rows are warp-private (warp w owns rows
// 16w..16w+15 of P both for write and read), so the P-visibility barrier is
// now __syncwarp() instead of __syncthreads().
// ---------------------------------------------------------------------------
__global__ __launch_bounds__(128) void flash_attn_split() {
    __shared__ float QsT[64][64];   // swizzled [e][qrow]
    __shared__ float KsT[64][64];   // swizzled [e][krow]; reused plain as P
    __shared__ float Vs[64][64];    // [krow][e]

    const int tid = threadIdx.x;
    const int ty = tid >> 4;
    const int tx = tid & 15;
    const int q0 = blockIdx.x << 6;
    const int h  = blockIdx.y;
    const int b  = blockIdx.z >> 1;
    const int sp = blockIdx.z & 1;

    const size_t baseQ  = ((size_t)(b * T_ + q0) * H_ + h) * E_;
    const size_t baseKV = ((size_t)(b * T_ + sp * TSPLIT) * H_ + h) * E_;

    for (int idx = tid; idx < 1024; idx += 128) {
        int row = idx >> 4;
        int t = idx & 15;
        int c = t << 2;
        float4 v = *(const float4*)(g_Q + baseQ + (size_t)row * HE_ + c);
        int col = (((row >> 2) ^ t) << 2) | (row & 3);
        QsT[c + 0][col] = v.x;
        QsT[c + 1][col] = v.y;
        QsT[c + 2][col] = v.z;
        QsT[c + 3][col] = v.w;
    }

    float m[8], l[8];
    u64 o2[8][2];
#pragma unroll
    for (int i = 0; i < 8; i++) {
        m[i] = -1e30f;
        l[i] = 0.f;
        o2[i][0] = 0ull;
        o2[i][1] = 0ull;
    }

    for (int k0 = 0; k0 < TSPLIT; k0 += 64) {
        __syncthreads();   // prev tile fully consumed (incl. P reads)
        for (int idx = tid; idx < 1024; idx += 128) {
            int row = idx >> 4;
            int t = idx & 15;
            int c = t << 2;
            size_t g = baseKV + (size_t)(k0 + row) * HE_ + c;
            float4 kv = *(const float4*)(g_K + g);
            int col = (((row >> 2) ^ t) << 2) | (row & 3);
            KsT[c + 0][col] = kv.x;
            KsT[c + 1][col] = kv.y;
            KsT[c + 2][col] = kv.z;
            KsT[c + 3][col] = kv.w;
            *(float4*)&Vs[row][c] = *(const float4*)(g_V + g);
        }
        __syncthreads();

        u64 s2[8][2];
#pragma unroll
        for (int i = 0; i < 8; i++) { s2[i][0] = 0ull; s2[i][1] = 0ull; }
#pragma unroll 4
        for (int x = 0; x < 16; x++) {
#pragma unroll
            for (int ee = 0; ee < 4; ee++) {
                int e = (x << 2) + ee;
                float4 qa = *(const float4*)&QsT[e][((2 * ty) ^ x) << 2];
                float4 qb = *(const float4*)&QsT[e][((2 * ty + 1) ^ x) << 2];
                float4 k4 = *(const float4*)&KsT[e][(tx ^ x) << 2];
                u64 kp0 = pack2(k4.x, k4.y);
                u64 kp1 = pack2(k4.z, k4.w);
                float q[8] = {qa.x, qa.y, qa.z, qa.w, qb.x, qb.y, qb.z, qb.w};
#pragma unroll
                for (int i = 0; i < 8; i++) {
                    u64 qd = pack2(q[i], q[i]);
                    fma2(s2[i][0], qd, kp0);
                    fma2(s2[i][1], qd, kp1);
                }
            }
        }

        float s[8][4];
#pragma unroll
        for (int i = 0; i < 8; i++) {
            float2 p0 = unpack2(s2[i][0]);
            float2 p1 = unpack2(s2[i][1]);
            s[i][0] = p0.x; s[i][1] = p0.y; s[i][2] = p1.x; s[i][3] = p1.y;
        }
#pragma unroll
        for (int i = 0; i < 8; i++) {
            float mx = fmaxf(fmaxf(s[i][0], s[i][1]), fmaxf(s[i][2], s[i][3]));
#pragma unroll
            for (int off = 8; off >= 1; off >>= 1)
                mx = fmaxf(mx, __shfl_xor_sync(0xffffffffu, mx, off));
            float mnew = fmaxf(m[i], mx);
            float corr = __expf(m[i] - mnew);
            float rs = 0.f;
#pragma unroll
            for (int j = 0; j < 4; j++) {
                s[i][j] = __expf(s[i][j] - mnew);
                rs += s[i][j];
            }
#pragma unroll
            for (int off = 8; off >= 1; off >>= 1)
                rs += __shfl_xor_sync(0xffffffffu, rs, off);
            l[i] = l[i] * corr + rs;
            m[i] = mnew;
            u64 cd = pack2(corr, corr);
            o2[i][0] = mul2(o2[i][0], cd);
            o2[i][1] = mul2(o2[i][1], cd);
        }

        __syncthreads();   // all warps done reading KsT as K (cross-warp)
#pragma unroll
        for (int i = 0; i < 8; i++)
            *(float4*)&KsT[(ty << 3) + i][tx << 2] =
                make_float4(s[i][0], s[i][1], s[i][2], s[i][3]);
        __syncwarp();      // P rows are warp-private: warp-scope visibility

#pragma unroll 4
        for (int k = 0; k < 64; k += 4) {
            u64 vp[4][2];
#pragma unroll
            for (int kk = 0; kk < 4; kk++) {
                float4 v4 = *(const float4*)&Vs[k + kk][tx << 2];
                vp[kk][0] = pack2(v4.x, v4.y);
                vp[kk][1] = pack2(v4.z, v4.w);
            }
#pragma unroll
            for (int i = 0; i < 8; i++) {
                float4 p4 = *(const float4*)&KsT[(ty << 3) + i][k];
                float p[4] = {p4.x, p4.y, p4.z, p4.w};
#pragma unroll
                for (int kk = 0; kk < 4; kk++) {
                    u64 pd = pack2(p[kk], p[kk]);
                    fma2(o2[i][0], pd, vp[kk][0]);
                    fma2(o2[i][1], pd, vp[kk][1]);
                }
            }
        }
    }

    const size_t opBase = (size_t)sp * BT_ * HE_;
    const size_t mlBase = (size_t)sp * BT_ * H_;
#pragma unroll
    for (int i = 0; i < 8; i++) {
        int row = q0 + (ty << 3) + i;
        float2 p0 = unpack2(o2[i][0]);
        float2 p1 = unpack2(o2[i][1]);
        *(float4*)&g_Op[opBase + ((size_t)(b * T_ + row) * H_ + h) * E_ +
                        (tx << 2)] = make_float4(p0.x, p0.y, p1.x, p1.y);
        if (tx == 0) {
            size_t mi = mlBase + (size_t)(b * T_ + row) * H_ + h;
            g_m[mi] = m[i];
            g_l[mi] = l[i];
        }
    }
}

// ---------------------------------------------------------------------------
// Combine (unchanged).
// ---------------------------------------------------------------------------
__global__ __launch_bounds__(256) void flash_combine(float* __restrict__ Out) {
    int idx = blockIdx.x * 256 + threadIdx.x;   // float4 index
    int rowh = idx >> 4;                         // (b*T+t)*H + h
    float m0 = g_m[rowh];
    float m1 = g_m[BT_ * H_ + rowh];
    float l0 = g_l[rowh];
    float l1 = g_l[BT_ * H_ + rowh];
    float M = fmaxf(m0, m1);
    float w0 = __expf(m0 - M);
    float w1 = __expf(m1 - M);
    float inv = 1.0f / (l0 * w0 + l1 * w1);

    const float4* Op4 = (const float4*)g_Op;
    float4 o0 = Op4[idx];
    float4 o1 = Op4[(BT_ * HE_ / 4) + idx];
    float4 r;
    r.x = (o0.x * w0 + o1.x * w1) * inv;
    r.y = (o0.y * w0 + o1.y * w1) * inv;
    r.z = (o0.z * w0 + o1.z * w1) * inv;
    r.w = (o0.w * w0 + o1.w * w1) * inv;
    ((float4*)Out)[idx] = r;
}

// ---------------------------------------------------------------------------
extern "C" void kernel_launch(void* const* d_in, const int* in_sizes, int n_in,
                              void* d_out, int out_size) {
    const float* query     = (const float*)d_in[0];
    const float* key_value = (const float*)d_in[1];
    const float* Wq        = (const float*)d_in[2];
    const float* Wk        = (const float*)d_in[3];
    const float* Wv        = (const float*)d_in[4];
    float* out = (float*)d_out;

    const float scale = 0.35355339059327379f;  // 64^(-1/4)

    dim3 gproj(HE_ / 64, BT_ / 64, 2);         // (16, 128, 2): z0=Q, z1=K+V
    proj_gemm<<<gproj, 128>>>(query, key_value, Wq, Wk, Wv, scale);

    dim3 gattn(T_ / 64, H_, B_ * NSPLIT);      // (32, 16, 8)
    flash_attn_split<<<gattn, 128>>>();

    flash_combine<<<BT_ * HE_ / 4 / 256, 256>>>(out);
}

// round 15
// speedup vs baseline: 1.1681x; 1.1681x over previous
#include <cuda_runtime.h>
#include <cstdint>

#define B_   4
#define T_   2048
#define HIN_ 1024
#define H_   16
#define E_   64
#define HE_  (H_ * E_)   // 1024
#define BT_  (B_ * T_)   // 8192
#define NSPLIT 2
#define TSPLIT (T_ / NSPLIT)   // 1024 keys per split

// Persistent scratch (no allocations allowed in kernel_launch).
__device__ float g_Q[BT_ * HE_];
__device__ float g_K[BT_ * HE_];
__device__ float g_V[BT_ * HE_];
__device__ float g_Op[NSPLIT * BT_ * HE_];   // unnormalized partial O
__device__ float g_m[NSPLIT * BT_ * H_];     // running max per row
__device__ float g_l[NSPLIT * BT_ * H_];     // running sum per row

// ---------------------------------------------------------------------------
// Packed fp32x2 helpers (Blackwell FFMA2 via PTX f32x2)
// ---------------------------------------------------------------------------
typedef unsigned long long u64;

__device__ __forceinline__ u64 pack2(float lo, float hi) {
    u64 r;
    asm("mov.b64 %0, {%1,%2};" : "=l"(r) : "f"(lo), "f"(hi));
    return r;
}
__device__ __forceinline__ float2 unpack2(u64 v) {
    float2 r;
    asm("mov.b64 {%0,%1}, %2;" : "=f"(r.x), "=f"(r.y) : "l"(v));
    return r;
}
__device__ __forceinline__ void fma2(u64& d, u64 a, u64 b) {
    asm("fma.rn.f32x2 %0, %1, %2, %0;" : "+l"(d) : "l"(a), "l"(b));
}
__device__ __forceinline__ u64 mul2(u64 a, u64 b) {
    u64 r;
    asm("mul.rn.f32x2 %0, %1, %2;" : "=l"(r) : "l"(a), "l"(b));
    return r;
}

// ---------------------------------------------------------------------------
// Projection GEMM, KV-fused (z=0: Q; z=1: K+V share the A tile) — R13 shape.
// NEW (R15): span operands (W columns) are read from smem as ulonglong2 —
// the LDS.128 destination register pairs ARE the packed f32x2 operands;
// the per-kk pack2 MOVs on the span side disappear at zero register cost.
// ---------------------------------------------------------------------------
__global__ __launch_bounds__(128) void proj_gemm(const float* __restrict__ Aq,
                                                 const float* __restrict__ Akv,
                                                 const float* __restrict__ Wq,
                                                 const float* __restrict__ Wk,
                                                 const float* __restrict__ Wv,
                                                 float scale) {
    __shared__ __align__(16) float AsT[2][16][64];      // [buf][k][m-swizzled]
    __shared__ __align__(16) float Ws[2][2][16][68];    // [buf][mat][k][n]

    const int fused = blockIdx.z;         // 0: Q, 1: K+V
    const float* __restrict__ A  = fused ? Akv : Aq;
    const float* __restrict__ W0 = fused ? Wk : Wq;
    const float* __restrict__ W1 = Wv;    // used only when fused
    float* __restrict__ C0 = fused ? g_K : g_Q;
    float* __restrict__ C1 = g_V;

    const int tid = threadIdx.x;
    const int ty = tid >> 4;          // 0..7  (8 rows each)
    const int tx = tid & 15;          // 0..15 (4 cols each)
    const int bm = blockIdx.y << 6;
    const int bn = blockIdx.x << 6;

    const int ar = tid >> 1;
    const int ac = (tid & 1) << 3;
    const int wr = tid >> 3;
    const int wc = (tid & 7) << 3;

    const float* Ap  = A + (size_t)(bm + ar) * HIN_ + ac;
    const float* W0p = W0 + (size_t)wr * HE_ + bn + wc;
    const float* W1p = W1 + (size_t)wr * HE_ + bn + wc;

    u64 acc0[8][2], acc1[8][2];
#pragma unroll
    for (int i = 0; i < 8; i++) {
        acc0[i][0] = 0ull; acc0[i][1] = 0ull;
        acc1[i][0] = 0ull; acc1[i][1] = 0ull;
    }

    // swizzle: storage col of (k, m) = m ^ (((k>>2)&3)<<2)
    {   // prologue: chunk 0
        float4 a0 = *(const float4*)(Ap);
        float4 a1 = *(const float4*)(Ap + 4);
        float av[8] = {a0.x, a0.y, a0.z, a0.w, a1.x, a1.y, a1.z, a1.w};
#pragma unroll
        for (int j = 0; j < 8; j++) {
            int k = ac + j;
            AsT[0][k][ar ^ (((k >> 2) & 3) << 2)] = av[j];
        }
        *(float4*)&Ws[0][0][wr][wc]     = *(const float4*)(W0p);
        *(float4*)&Ws[0][0][wr][wc + 4] = *(const float4*)(W0p + 4);
        if (fused) {
            *(float4*)&Ws[0][1][wr][wc]     = *(const float4*)(W1p);
            *(float4*)&Ws[0][1][wr][wc + 4] = *(const float4*)(W1p + 4);
        }
    }
    __syncthreads();

    int buf = 0;
    for (int it = 1; it <= 64; it++) {
        float4 a0, a1, wa0, wa1, wb0, wb1;
        if (it < 64) {   // prefetch chunk it
            a0 = *(const float4*)(Ap + it * 16);
            a1 = *(const float4*)(Ap + it * 16 + 4);
            wa0 = *(const float4*)(W0p + (size_t)it * 16 * HE_);
            wa1 = *(const float4*)(W0p + (size_t)it * 16 * HE_ + 4);
            if (fused) {
                wb0 = *(const float4*)(W1p + (size_t)it * 16 * HE_);
                wb1 = *(const float4*)(W1p + (size_t)it * 16 * HE_ + 4);
            }
        }

        // compute chunk it-1 from buf
#pragma unroll
        for (int kk = 0; kk < 16; kk++) {
            int cx = ((kk >> 2) & 3) << 2;
            float4 aa0 = *(const float4*)&AsT[buf][kk][(ty << 3) ^ cx];
            float4 aa1 = *(const float4*)&AsT[buf][kk][((ty << 3) + 4) ^ cx];
            ulonglong2 w2 =
                *(const ulonglong2*)&Ws[buf][0][kk][tx << 2];  // packed span
            float a[8] = {aa0.x, aa0.y, aa0.z, aa0.w,
                          aa1.x, aa1.y, aa1.z, aa1.w};
#pragma unroll
            for (int i = 0; i < 8; i++) {
                u64 ad = pack2(a[i], a[i]);
                fma2(acc0[i][0], ad, w2.x);
                fma2(acc0[i][1], ad, w2.y);
            }
            if (fused) {
                ulonglong2 v2 =
                    *(const ulonglong2*)&Ws[buf][1][kk][tx << 2];
#pragma unroll
                for (int i = 0; i < 8; i++) {
                    u64 ad = pack2(a[i], a[i]);
                    fma2(acc1[i][0], ad, v2.x);
                    fma2(acc1[i][1], ad, v2.y);
                }
            }
        }

        if (it < 64) {
            int nb = buf ^ 1;
            float av[8] = {a0.x, a0.y, a0.z, a0.w, a1.x, a1.y, a1.z, a1.w};
#pragma unroll
            for (int j = 0; j < 8; j++) {
                int k = ac + j;
                AsT[nb][k][ar ^ (((k >> 2) & 3) << 2)] = av[j];
            }
            *(float4*)&Ws[nb][0][wr][wc]     = wa0;
            *(float4*)&Ws[nb][0][wr][wc + 4] = wa1;
            if (fused) {
                *(float4*)&Ws[nb][1][wr][wc]     = wb0;
                *(float4*)&Ws[nb][1][wr][wc + 4] = wb1;
            }
            __syncthreads();
            buf = nb;
        }
    }

    // Epilogue: Q and K carry the softmax scale; V is unscaled.
#pragma unroll
    for (int i = 0; i < 8; i++) {
        float2 p0 = unpack2(acc0[i][0]);
        float2 p1 = unpack2(acc0[i][1]);
        float4 r = make_float4(p0.x * scale, p0.y * scale,
                               p1.x * scale, p1.y * scale);
        *(float4*)&C0[(size_t)(bm + (ty << 3) + i) * HE_ + bn + (tx << 2)] = r;
    }
    if (fused) {
#pragma unroll
        for (int i = 0; i < 8; i++) {
            float2 p0 = unpack2(acc1[i][0]);
            float2 p1 = unpack2(acc1[i][1]);
            float4 r = make_float4(p0.x, p0.y, p1.x, p1.y);
            *(float4*)&C1[(size_t)(bm + (ty << 3) + i) * HE_ + bn + (tx << 2)] = r;
        }
    }
}

// ---------------------------------------------------------------------------
// Flash attention, split-K (R13 structure; R15: K/V span reads as ulonglong2).
// ---------------------------------------------------------------------------
__global__ __launch_bounds__(128) void flash_attn_split() {
    __shared__ __align__(16) float QsT[64][64];  // swizzled [e][qrow]
    __shared__ __align__(16) float KsT[64][64];  // swizzled [e][krow]; P reuse
    __shared__ __align__(16) float Vs[64][64];   // [krow][e]

    const int tid = threadIdx.x;
    const int ty = tid >> 4;
    const int tx = tid & 15;
    const int q0 = blockIdx.x << 6;
    const int h  = blockIdx.y;
    const int b  = blockIdx.z >> 1;
    const int sp = blockIdx.z & 1;

    const size_t baseQ  = ((size_t)(b * T_ + q0) * H_ + h) * E_;
    const size_t baseKV = ((size_t)(b * T_ + sp * TSPLIT) * H_ + h) * E_;

    for (int idx = tid; idx < 1024; idx += 128) {
        int row = idx >> 4;
        int t = idx & 15;
        int c = t << 2;
        float4 v = *(const float4*)(g_Q + baseQ + (size_t)row * HE_ + c);
        int col = (((row >> 2) ^ t) << 2) | (row & 3);
        QsT[c + 0][col] = v.x;
        QsT[c + 1][col] = v.y;
        QsT[c + 2][col] = v.z;
        QsT[c + 3][col] = v.w;
    }

    float m[8], l[8];
    u64 o2[8][2];
#pragma unroll
    for (int i = 0; i < 8; i++) {
        m[i] = -1e30f;
        l[i] = 0.f;
        o2[i][0] = 0ull;
        o2[i][1] = 0ull;
    }

    for (int k0 = 0; k0 < TSPLIT; k0 += 64) {
        __syncthreads();
        for (int idx = tid; idx < 1024; idx += 128) {
            int row = idx >> 4;
            int t = idx & 15;
            int c = t << 2;
            size_t g = baseKV + (size_t)(k0 + row) * HE_ + c;
            float4 kv = *(const float4*)(g_K + g);
            int col = (((row >> 2) ^ t) << 2) | (row & 3);
            KsT[c + 0][col] = kv.x;
            KsT[c + 1][col] = kv.y;
            KsT[c + 2][col] = kv.z;
            KsT[c + 3][col] = kv.w;
            *(float4*)&Vs[row][c] = *(const float4*)(g_V + g);
        }
        __syncthreads();

        u64 s2[8][2];
#pragma unroll
        for (int i = 0; i < 8; i++) { s2[i][0] = 0ull; s2[i][1] = 0ull; }
#pragma unroll 4
        for (int x = 0; x < 16; x++) {
#pragma unroll
            for (int ee = 0; ee < 4; ee++) {
                int e = (x << 2) + ee;
                float4 qa = *(const float4*)&QsT[e][((2 * ty) ^ x) << 2];
                float4 qb = *(const float4*)&QsT[e][((2 * ty + 1) ^ x) << 2];
                ulonglong2 kp =
                    *(const ulonglong2*)&KsT[e][(tx ^ x) << 2];  // packed span
                float q[8] = {qa.x, qa.y, qa.z, qa.w, qb.x, qb.y, qb.z, qb.w};
#pragma unroll
                for (int i = 0; i < 8; i++) {
                    u64 qd = pack2(q[i], q[i]);
                    fma2(s2[i][0], qd, kp.x);
                    fma2(s2[i][1], qd, kp.y);
                }
            }
        }

        float s[8][4];
#pragma unroll
        for (int i = 0; i < 8; i++) {
            float2 p0 = unpack2(s2[i][0]);
            float2 p1 = unpack2(s2[i][1]);
            s[i][0] = p0.x; s[i][1] = p0.y; s[i][2] = p1.x; s[i][3] = p1.y;
        }
#pragma unroll
        for (int i = 0; i < 8; i++) {
            float mx = fmaxf(fmaxf(s[i][0], s[i][1]), fmaxf(s[i][2], s[i][3]));
#pragma unroll
            for (int off = 8; off >= 1; off >>= 1)
                mx = fmaxf(mx, __shfl_xor_sync(0xffffffffu, mx, off));
            float mnew = fmaxf(m[i], mx);
            float corr = __expf(m[i] - mnew);
            float rs = 0.f;
#pragma unroll
            for (int j = 0; j < 4; j++) {
                s[i][j] = __expf(s[i][j] - mnew);
                rs += s[i][j];
            }
#pragma unroll
            for (int off = 8; off >= 1; off >>= 1)
                rs += __shfl_xor_sync(0xffffffffu, rs, off);
            l[i] = l[i] * corr + rs;
            m[i] = mnew;
            u64 cd = pack2(corr, corr);
            o2[i][0] = mul2(o2[i][0], cd);
            o2[i][1] = mul2(o2[i][1], cd);
        }

        __syncthreads();
#pragma unroll
        for (int i = 0; i < 8; i++)
            *(float4*)&KsT[(ty << 3) + i][tx << 2] =
                make_float4(s[i][0], s[i][1], s[i][2], s[i][3]);
        __syncthreads();

#pragma unroll 4
        for (int k = 0; k < 64; k += 4) {
            ulonglong2 vp[4];
#pragma unroll
            for (int kk = 0; kk < 4; kk++)
                vp[kk] = *(const ulonglong2*)&Vs[k + kk][tx << 2];  // packed
#pragma unroll
            for (int i = 0; i < 8; i++) {
                float4 p4 = *(const float4*)&KsT[(ty << 3) + i][k];
                float p[4] = {p4.x, p4.y, p4.z, p4.w};
#pragma unroll
                for (int kk = 0; kk < 4; kk++) {
                    u64 pd = pack2(p[kk], p[kk]);
                    fma2(o2[i][0], pd, vp[kk].x);
                    fma2(o2[i][1], pd, vp[kk].y);
                }
            }
        }
    }

    const size_t opBase = (size_t)sp * BT_ * HE_;
    const size_t mlBase = (size_t)sp * BT_ * H_;
#pragma unroll
    for (int i = 0; i < 8; i++) {
        int row = q0 + (ty << 3) + i;
        float2 p0 = unpack2(o2[i][0]);
        float2 p1 = unpack2(o2[i][1]);
        *(float4*)&g_Op[opBase + ((size_t)(b * T_ + row) * H_ + h) * E_ +
                        (tx << 2)] = make_float4(p0.x, p0.y, p1.x, p1.y);
        if (tx == 0) {
            size_t mi = mlBase + (size_t)(b * T_ + row) * H_ + h;
            g_m[mi] = m[i];
            g_l[mi] = l[i];
        }
    }
}

// ---------------------------------------------------------------------------
// Combine (unchanged).
// ---------------------------------------------------------------------------
__global__ __launch_bounds__(256) void flash_combine(float* __restrict__ Out) {
    int idx = blockIdx.x * 256 + threadIdx.x;   // float4 index
    int rowh = idx >> 4;                         // (b*T+t)*H + h
    float m0 = g_m[rowh];
    float m1 = g_m[BT_ * H_ + rowh];
    float l0 = g_l[rowh];
    float l1 = g_l[BT_ * H_ + rowh];
    float M = fmaxf(m0, m1);
    float w0 = __expf(m0 - M);
    float w1 = __expf(m1 - M);
    float inv = 1.0f / (l0 * w0 + l1 * w1);

    const float4* Op4 = (const float4*)g_Op;
    float4 o0 = Op4[idx];
    float4 o1 = Op4[(BT_ * HE_ / 4) + idx];
    float4 r;
    r.x = (o0.x * w0 + o1.x * w1) * inv;
    r.y = (o0.y * w0 + o1.y * w1) * inv;
    r.z = (o0.z * w0 + o1.z * w1) * inv;
    r.w = (o0.w * w0 + o1.w * w1) * inv;
    ((float4*)Out)[idx] = r;
}

// ---------------------------------------------------------------------------
extern "C" void kernel_launch(void* const* d_in, const int* in_sizes, int n_in,
                              void* d_out, int out_size) {
    const float* query     = (const float*)d_in[0];
    const float* key_value = (const float*)d_in[1];
    const float* Wq        = (const float*)d_in[2];
    const float* Wk        = (const float*)d_in[3];
    const float* Wv        = (const float*)d_in[4];
    float* out = (float*)d_out;

    const float scale = 0.35355339059327379f;  // 64^(-1/4)

    dim3 gproj(HE_ / 64, BT_ / 64, 2);         // (16, 128, 2): z0=Q, z1=K+V
    proj_gemm<<<gproj, 128>>>(query, key_value, Wq, Wk, Wv, scale);

    dim3 gattn(T_ / 64, H_, B_ * NSPLIT);      // (32, 16, 8)
    flash_attn_split<<<gattn, 128>>>();

    flash_combine<<<BT_ * HE_ / 4 / 256, 256>>>(out);
}